// round 14
// baseline (speedup 1.0000x reference)
#include <cuda_runtime.h>
#include <cuda_bf16.h>
#include <cstdint>

// Embedding gather: out[i, :] = table[indices[i], :]
// indices: int32 [819200], table: fp32 [1M, 64] (256B rows), out same rows.
//
// Deterministic L2 partition: rows with index < PROTECT_ROWS (~92MB < 126MB
// L2) load with evict_last -> they stay L2-resident across graph replays
// (L2 is not flushed per launch), making ~44% of lookups guaranteed hits in
// steady state. All other rows load with evict_first: they still allocate
// (within-iteration duplicate hits) but are evicted before the protected
// set. Output uses 256-bit evict-first streaming stores.
// 8 lanes/row, 2x128-bit loads per lane, 4-row unroll (8 loads in flight).

#define PROTECT_ROWS 360448   // * 256B = 92.3 MB protected table prefix

__device__ __forceinline__ float4 ldg_hint(const float4* p, unsigned long long pol) {
    float4 v;
    asm volatile("ld.global.nc.L2::cache_hint.v4.f32 {%0,%1,%2,%3}, [%4], %5;"
                 : "=f"(v.x), "=f"(v.y), "=f"(v.z), "=f"(v.w)
                 : "l"(p), "l"(pol));
    return v;
}

__device__ __forceinline__ void stcs256(void* p, const float4& a, const float4& b) {
    asm volatile("st.global.cs.v8.b32 [%0], {%1,%2,%3,%4,%5,%6,%7,%8};"
                 :: "l"(p),
                    "f"(a.x), "f"(a.y), "f"(a.z), "f"(a.w),
                    "f"(b.x), "f"(b.y), "f"(b.z), "f"(b.w)
                 : "memory");
}

__global__ void __launch_bounds__(256)
emb_gather_u4_part_kernel(const int* __restrict__ idx,
                          const float4* __restrict__ table,
                          char* __restrict__ out,
                          int nrows, int quarter) {
    int t = blockIdx.x * blockDim.x + threadIdx.x;
    int row = t >> 3;          // 8 lanes per row
    int lane = t & 7;          // each lane owns 32B = 2 float4 slots
    if (row >= quarter) return;

    // Protected: evict_last (pin across replays). Other: evict_first
    // (allocate, but first eviction candidate -> can't displace pinned set).
    unsigned long long pol_p, pol_n;
    asm volatile("createpolicy.fractional.L2::evict_last.b64 %0, 1.0;" : "=l"(pol_p));
    asm volatile("createpolicy.fractional.L2::evict_first.b64 %0, 1.0;" : "=l"(pol_n));

    int r0 = row;
    int r1 = row + quarter;
    int r2 = row + 2 * quarter;
    int r3 = row + 3 * quarter;

    int i0 = __ldg(&idx[r0]);
    int i1 = __ldg(&idx[r1]);
    int i2 = (r2 < nrows) ? __ldg(&idx[r2]) : 0;
    int i3 = (r3 < nrows) ? __ldg(&idx[r3]) : 0;

    // Branch-free policy select per gathered row
    unsigned long long p0 = (i0 < PROTECT_ROWS) ? pol_p : pol_n;
    unsigned long long p1 = (i1 < PROTECT_ROWS) ? pol_p : pol_n;
    unsigned long long p2 = (i2 < PROTECT_ROWS) ? pol_p : pol_n;
    unsigned long long p3 = (i3 < PROTECT_ROWS) ? pol_p : pol_n;

    int slot = lane * 2;       // float4 slot within the 16-slot row

    // 8 independent 128-bit random table loads in flight
    float4 a0 = ldg_hint(&table[(size_t)i0 * 16 + slot],     p0);
    float4 b0 = ldg_hint(&table[(size_t)i0 * 16 + slot + 1], p0);
    float4 a1 = ldg_hint(&table[(size_t)i1 * 16 + slot],     p1);
    float4 b1 = ldg_hint(&table[(size_t)i1 * 16 + slot + 1], p1);
    float4 a2 = ldg_hint(&table[(size_t)i2 * 16 + slot],     p2);
    float4 b2 = ldg_hint(&table[(size_t)i2 * 16 + slot + 1], p2);
    float4 a3 = ldg_hint(&table[(size_t)i3 * 16 + slot],     p3);
    float4 b3 = ldg_hint(&table[(size_t)i3 * 16 + slot + 1], p3);

    size_t off = (size_t)lane * 32;

    // 256-bit streaming stores — write-once output, don't pollute L2
    stcs256(out + (size_t)r0 * 256 + off, a0, b0);
    stcs256(out + (size_t)r1 * 256 + off, a1, b1);
    if (r2 < nrows) stcs256(out + (size_t)r2 * 256 + off, a2, b2);
    if (r3 < nrows) stcs256(out + (size_t)r3 * 256 + off, a3, b3);
}

extern "C" void kernel_launch(void* const* d_in, const int* in_sizes, int n_in,
                              void* d_out, int out_size) {
    // Identify inputs by element count so ordering can't break us.
    const void* p_idx = d_in[0];
    const void* p_tab = d_in[1];
    int n_idx = in_sizes[0];
    if (n_in >= 2 && in_sizes[0] > in_sizes[1]) {
        p_tab = d_in[0];
        p_idx = d_in[1];
        n_idx = in_sizes[1];
    }

    const int*    idx = (const int*)p_idx;      // indices, int32, 819200 elems
    const float4* tab = (const float4*)p_tab;   // table, fp32 [1M,64]
    char*         out = (char*)d_out;

    int nrows = n_idx;                          // 819200
    int quarter = (nrows + 3) / 4;              // rows per unroll slot
    long long total_threads = (long long)quarter * 8;
    int block = 256;
    int grid = (int)((total_threads + block - 1) / block);

    emb_gather_u4_part_kernel<<<grid, block>>>(idx, tab, out, nrows, quarter);
}

// round 15
// speedup vs baseline: 1.0497x; 1.0497x over previous
#include <cuda_runtime.h>
#include <cuda_bf16.h>
#include <cstdint>

// Embedding gather: out[i, :] = table[indices[i], :]
// indices: int32 [819200], table: fp32 [1M, 64] (256B rows), out same rows.
//
// R12 structure (best kernel dur): 8 lanes/row, 2x128-bit evict_last loads
// per lane, 4-row unroll (8 loads in flight), 256-bit .cs streaming stores.
// New: the first load of each lane pair carries L2::256B prefetch-size —
// rows are 256B-aligned and fully consumed, so this groups each row gather
// into one 256B DRAM burst (better row-buffer locality, zero overfetch).

__device__ __forceinline__ float4 ldg_hint_pf256(const float4* p, unsigned long long pol) {
    float4 v;
    asm volatile("ld.global.nc.L2::cache_hint.L2::256B.v4.f32 {%0,%1,%2,%3}, [%4], %5;"
                 : "=f"(v.x), "=f"(v.y), "=f"(v.z), "=f"(v.w)
                 : "l"(p), "l"(pol));
    return v;
}

__device__ __forceinline__ float4 ldg_hint(const float4* p, unsigned long long pol) {
    float4 v;
    asm volatile("ld.global.nc.L2::cache_hint.v4.f32 {%0,%1,%2,%3}, [%4], %5;"
                 : "=f"(v.x), "=f"(v.y), "=f"(v.z), "=f"(v.w)
                 : "l"(p), "l"(pol));
    return v;
}

__device__ __forceinline__ void stcs256(void* p, const float4& a, const float4& b) {
    asm volatile("st.global.cs.v8.b32 [%0], {%1,%2,%3,%4,%5,%6,%7,%8};"
                 :: "l"(p),
                    "f"(a.x), "f"(a.y), "f"(a.z), "f"(a.w),
                    "f"(b.x), "f"(b.y), "f"(b.z), "f"(b.w)
                 : "memory");
}

__global__ void __launch_bounds__(256)
emb_gather_u4_pf_kernel(const int* __restrict__ idx,
                        const float4* __restrict__ table,
                        char* __restrict__ out,
                        int nrows, int quarter) {
    int t = blockIdx.x * blockDim.x + threadIdx.x;
    int row = t >> 3;          // 8 lanes per row
    int lane = t & 7;          // each lane owns 32B = 2 float4 slots
    if (row >= quarter) return;

    unsigned long long pol;
    asm volatile("createpolicy.fractional.L2::evict_last.b64 %0, 1.0;" : "=l"(pol));

    int r0 = row;
    int r1 = row + quarter;
    int r2 = row + 2 * quarter;
    int r3 = row + 3 * quarter;

    int i0 = __ldg(&idx[r0]);
    int i1 = __ldg(&idx[r1]);
    int i2 = (r2 < nrows) ? __ldg(&idx[r2]) : 0;
    int i3 = (r3 < nrows) ? __ldg(&idx[r3]) : 0;

    int slot = lane * 2;       // float4 slot within the 16-slot row

    // 8 independent 128-bit random table loads in flight;
    // first of each pair pulls the full 256B row into L2.
    float4 a0 = ldg_hint_pf256(&table[(size_t)i0 * 16 + slot], pol);
    float4 b0 = ldg_hint(&table[(size_t)i0 * 16 + slot + 1],   pol);
    float4 a1 = ldg_hint_pf256(&table[(size_t)i1 * 16 + slot], pol);
    float4 b1 = ldg_hint(&table[(size_t)i1 * 16 + slot + 1],   pol);
    float4 a2 = ldg_hint_pf256(&table[(size_t)i2 * 16 + slot], pol);
    float4 b2 = ldg_hint(&table[(size_t)i2 * 16 + slot + 1],   pol);
    float4 a3 = ldg_hint_pf256(&table[(size_t)i3 * 16 + slot], pol);
    float4 b3 = ldg_hint(&table[(size_t)i3 * 16 + slot + 1],   pol);

    size_t off = (size_t)lane * 32;

    // 256-bit streaming stores — write-once output, don't pollute L2
    stcs256(out + (size_t)r0 * 256 + off, a0, b0);
    stcs256(out + (size_t)r1 * 256 + off, a1, b1);
    if (r2 < nrows) stcs256(out + (size_t)r2 * 256 + off, a2, b2);
    if (r3 < nrows) stcs256(out + (size_t)r3 * 256 + off, a3, b3);
}

extern "C" void kernel_launch(void* const* d_in, const int* in_sizes, int n_in,
                              void* d_out, int out_size) {
    // Identify inputs by element count so ordering can't break us.
    const void* p_idx = d_in[0];
    const void* p_tab = d_in[1];
    int n_idx = in_sizes[0];
    if (n_in >= 2 && in_sizes[0] > in_sizes[1]) {
        p_tab = d_in[0];
        p_idx = d_in[1];
        n_idx = in_sizes[1];
    }

    const int*    idx = (const int*)p_idx;      // indices, int32, 819200 elems
    const float4* tab = (const float4*)p_tab;   // table, fp32 [1M,64]
    char*         out = (char*)d_out;

    int nrows = n_idx;                          // 819200
    int quarter = (nrows + 3) / 4;              // rows per unroll slot
    long long total_threads = (long long)quarter * 8;
    int block = 256;
    int grid = (int)((total_threads + block - 1) / block);

    emb_gather_u4_pf_kernel<<<grid, block>>>(idx, tab, out, nrows, quarter);
}

// round 16
// speedup vs baseline: 1.0565x; 1.0065x over previous
#include <cuda_runtime.h>
#include <cuda_bf16.h>
#include <cstdint>

// Embedding gather: out[i, :] = table[indices[i], :]
// indices: int32 [819200], table: fp32 [1M, 64] (256B rows), out same rows.
// Converged-best configuration (R12):
//  - 8 lanes per row; each lane owns 32B (2 float4 slots).
//  - Table loads: 128-bit ld.global.nc with L2::evict_last cache-hint policy
//    (128-bit is the L1tex wavefront sweet spot for random gathers; 256-bit
//    loads and L2 partition/prefetch variants all measured worse).
//  - 4-row unroll -> 8 independent gathers issued per thread.
//  - Output: 256-bit st.global.cs streaming stores (half the store
//    instructions, write-once stream doesn't displace table rows in L2).
// Traffic is at the analytic floor (~342MB/iter); kernel runs at ~75% of
// HBM peak, the efficiency wall for mixed random-read + streaming-write.

__device__ __forceinline__ float4 ldg_evict_last(const float4* p, unsigned long long pol) {
    float4 v;
    asm volatile("ld.global.nc.L2::cache_hint.v4.f32 {%0,%1,%2,%3}, [%4], %5;"
                 : "=f"(v.x), "=f"(v.y), "=f"(v.z), "=f"(v.w)
                 : "l"(p), "l"(pol));
    return v;
}

__device__ __forceinline__ void stcs256(void* p, const float4& a, const float4& b) {
    asm volatile("st.global.cs.v8.b32 [%0], {%1,%2,%3,%4,%5,%6,%7,%8};"
                 :: "l"(p),
                    "f"(a.x), "f"(a.y), "f"(a.z), "f"(a.w),
                    "f"(b.x), "f"(b.y), "f"(b.z), "f"(b.w)
                 : "memory");
}

__global__ void __launch_bounds__(256)
emb_gather_u4_s256_kernel(const int* __restrict__ idx,
                          const float4* __restrict__ table,
                          char* __restrict__ out,
                          int nrows, int quarter) {
    int t = blockIdx.x * blockDim.x + threadIdx.x;
    int row = t >> 3;          // 8 lanes per row
    int lane = t & 7;          // each lane owns 32B = 2 float4 slots
    if (row >= quarter) return;

    unsigned long long pol;
    asm volatile("createpolicy.fractional.L2::evict_last.b64 %0, 1.0;" : "=l"(pol));

    int r0 = row;
    int r1 = row + quarter;
    int r2 = row + 2 * quarter;
    int r3 = row + 3 * quarter;

    // Batch independent index loads (broadcast within 8-lane groups)
    int i0 = __ldg(&idx[r0]);
    int i1 = __ldg(&idx[r1]);
    int i2 = (r2 < nrows) ? __ldg(&idx[r2]) : 0;
    int i3 = (r3 < nrows) ? __ldg(&idx[r3]) : 0;

    int slot = lane * 2;       // float4 slot within the 16-slot row

    // 8 independent 128-bit random table loads
    float4 a0 = ldg_evict_last(&table[(size_t)i0 * 16 + slot],     pol);
    float4 b0 = ldg_evict_last(&table[(size_t)i0 * 16 + slot + 1], pol);
    float4 a1 = ldg_evict_last(&table[(size_t)i1 * 16 + slot],     pol);
    float4 b1 = ldg_evict_last(&table[(size_t)i1 * 16 + slot + 1], pol);
    float4 a2 = ldg_evict_last(&table[(size_t)i2 * 16 + slot],     pol);
    float4 b2 = ldg_evict_last(&table[(size_t)i2 * 16 + slot + 1], pol);
    float4 a3 = ldg_evict_last(&table[(size_t)i3 * 16 + slot],     pol);
    float4 b3 = ldg_evict_last(&table[(size_t)i3 * 16 + slot + 1], pol);

    size_t off = (size_t)lane * 32;

    // 256-bit streaming stores — write-once output, don't pollute L2
    stcs256(out + (size_t)r0 * 256 + off, a0, b0);
    stcs256(out + (size_t)r1 * 256 + off, a1, b1);
    if (r2 < nrows) stcs256(out + (size_t)r2 * 256 + off, a2, b2);
    if (r3 < nrows) stcs256(out + (size_t)r3 * 256 + off, a3, b3);
}

extern "C" void kernel_launch(void* const* d_in, const int* in_sizes, int n_in,
                              void* d_out, int out_size) {
    // Identify inputs by element count so ordering can't break us.
    const void* p_idx = d_in[0];
    const void* p_tab = d_in[1];
    int n_idx = in_sizes[0];
    if (n_in >= 2 && in_sizes[0] > in_sizes[1]) {
        p_tab = d_in[0];
        p_idx = d_in[1];
        n_idx = in_sizes[1];
    }

    const int*    idx = (const int*)p_idx;      // indices, int32, 819200 elems
    const float4* tab = (const float4*)p_tab;   // table, fp32 [1M,64]
    char*         out = (char*)d_out;

    int nrows = n_idx;                          // 819200
    int quarter = (nrows + 3) / 4;              // rows per unroll slot
    long long total_threads = (long long)quarter * 8;
    int block = 256;
    int grid = (int)((total_threads + block - 1) / block);

    emb_gather_u4_s256_kernel<<<grid, block>>>(idx, tab, out, nrows, quarter);
}